// round 9
// baseline (speedup 1.0000x reference)
#include <cuda_runtime.h>
#include <math.h>

#define NPROP 1500
#define NACT 64
#define NCLS 81
#define PERSON_IDX 2
#define O_CHUNK 100
#define THREADS 256
#define TILE_F4 ((O_CHUNK * NACT) / 4)   // 1600 float4 per tile

// per-proposal scratch (no cudaMalloc allowed)
__device__ float g_H[NPROP];
__device__ float g_O[NPROP];
__device__ float g_cx[NPROP], g_cy[NPROP];
__device__ float g_iw[NPROP], g_ih[NPROP];
__device__ float g_lw[NPROP], g_lh[NPROP];

// warp-per-row argmax + thread-per-row box stats; 188 blocks -> ~1-2us
__global__ void prep_kernel(const float* __restrict__ scores,
                            const float* __restrict__ bbox) {
    const int gtid  = blockIdx.x * blockDim.x + threadIdx.x;
    const int gwarp = gtid >> 5;
    const int lane  = threadIdx.x & 31;

    if (gwarp < NPROP) {
        const float* s = scores + (size_t)gwarp * NCLS;
        float best = s[lane];
        int   bi   = lane;
        float v1 = s[lane + 32];
        if (v1 > best) { best = v1; bi = lane + 32; }
        if (lane + 64 < NCLS) {
            float v2 = s[lane + 64];
            if (v2 > best) { best = v2; bi = lane + 64; }
        }
        #pragma unroll
        for (int sft = 16; sft > 0; sft >>= 1) {
            float ov = __shfl_xor_sync(0xffffffffu, best, sft);
            int   oi = __shfl_xor_sync(0xffffffffu, bi, sft);
            if (ov > best || (ov == best && oi < bi)) { best = ov; bi = oi; }
        }
        if (lane == 0) {
            g_H[gwarp] = (bi == PERSON_IDX) ? best : 0.0f;
            g_O[gwarp] = (bi == PERSON_IDX) ? 0.0f : best;
        }
    }

    if (gtid < NPROP) {
        float x0 = bbox[gtid * 4 + 0], y0 = bbox[gtid * 4 + 1];
        float x1 = bbox[gtid * 4 + 2], y1 = bbox[gtid * 4 + 3];
        float w = x1 - x0, h = y1 - y0;
        g_cx[gtid] = x0 + 0.5f * w;
        g_cy[gtid] = y0 + 0.5f * h;
        g_iw[gtid] = 1.0f / w;
        g_ih[gtid] = 1.0f / h;
        g_lw[gtid] = logf(w);
        g_lh[gtid] = logf(h);
    }
}

// out[h, o, a] = H[h]*O[o]*L[h,a]*exp(-|enc-mu|^2 * k)
//             = O[o] * (H*L*exp(-k*|mu|^2))[a] * exp( dot(enc, 2k*mu[a]) - k*|enc|^2 )
//
// PDL secondary: fill is unconditional (stores start immediately, no input
// dependence), then cudaGridDependencySynchronize() gates the g_H read.
// Person tiles (~1.2%) overwrite their tile after the staging barrier.
__global__ void __launch_bounds__(THREADS, 8)
score_kernel(const float* __restrict__ action_logits,
             const float* __restrict__ target_mean,
             float* __restrict__ out) {
    const int h   = blockIdx.y;
    const int o0  = blockIdx.x * O_CHUNK;
    const int tid = threadIdx.x;

    // 1) unconditional zero-fill: pure STG.128 stream from cycle ~5
    float* blk_out = out + (size_t)h * (NPROP * NACT) + (size_t)o0 * NACT;
    {
        const float4 z = make_float4(0.f, 0.f, 0.f, 0.f);
        float4* p = reinterpret_cast<float4*>(blk_out);
        #pragma unroll 4
        for (int i = tid; i < TILE_F4; i += THREADS)
            p[i] = z;
    }

    // 2) wait for prep kernel's grid (fast-path after the first ~2us)
    cudaGridDependencySynchronize();

    const float H = g_H[h];
    if (H == 0.0f) return;   // 98.8% of blocks retire here

    // ---- rare person path: overwrite the tile ----
    const float K = 5.5555555555555554f;  // 1/(2*0.3^2)

    __shared__ float sM0[NACT], sM1[NACT], sM2[NACT], sM3[NACT], sHQ[NACT];

    if (tid < NACT) {
        const float* mu = target_mean + ((size_t)h * NACT + tid) * 4;
        float m0 = mu[0], m1 = mu[1], m2 = mu[2], m3 = mu[3];
        float msq = m0 * m0 + m1 * m1 + m2 * m2 + m3 * m3;
        float twoK = 2.0f * K;
        sM0[tid] = twoK * m0;
        sM1[tid] = twoK * m1;
        sM2[tid] = twoK * m2;
        sM3[tid] = twoK * m3;
        sHQ[tid] = H * action_logits[(size_t)h * NACT + tid] * __expf(-K * msq);
    }

    const float cxh = g_cx[h], cyh = g_cy[h];
    const float iw = g_iw[h],  ih = g_ih[h];
    const float lw = g_lw[h],  lh = g_lh[h];

    // publishes smem staging AND orders the zero stores before the overwrites
    __syncthreads();

    const int a    = tid & (NACT - 1);
    const int osub = tid >> 6;              // 0..3
    const float M0 = sM0[a], M1 = sM1[a], M2 = sM2[a], M3 = sM3[a];
    const float HQ = sHQ[a];

    for (int j = osub; j < O_CHUNK; j += (THREADS / NACT)) {
        int o = o0 + j;
        float Ov = g_O[o];
        float tx = (g_cx[o] - cxh) * iw;
        float ty = (g_cy[o] - cyh) * ih;
        float tw = g_lw[o] - lw;
        float th = g_lh[o] - lh;
        float e2 = tx * tx + ty * ty + tw * tw + th * th;
        float ex = fmaf(tx, M0, fmaf(ty, M1, fmaf(tw, M2, th * M3))) - K * e2;
        blk_out[(size_t)j * NACT + a] = Ov * HQ * __expf(ex);
    }
}

extern "C" void kernel_launch(void* const* d_in, const int* in_sizes, int n_in,
                              void* d_out, int out_size) {
    const float* action_logits = (const float*)d_in[0];  // [1500,64]
    const float* target_mean   = (const float*)d_in[1];  // [1500,64,4]
    const float* bbox          = (const float*)d_in[2];  // [1500,4]
    const float* scores        = (const float*)d_in[3];  // [1500,81]
    float* out = (float*)d_out;                          // [1500,1500,64]

    // primary: tiny prep (1500 warps, warp-per-row)
    prep_kernel<<<(NPROP * 32 + THREADS - 1) / THREADS, THREADS>>>(scores, bbox);

    // secondary: PDL — launches concurrently, gridsync gates the g_H read
    cudaLaunchConfig_t cfg = {};
    cfg.gridDim  = dim3(NPROP / O_CHUNK, NPROP);  // (15, 1500)
    cfg.blockDim = dim3(THREADS);
    cfg.dynamicSmemBytes = 0;
    cfg.stream = 0;
    cudaLaunchAttribute attr;
    attr.id = cudaLaunchAttributeProgrammaticStreamSerialization;
    attr.val.programmaticStreamSerializationAllowed = 1;
    cfg.attrs = &attr;
    cfg.numAttrs = 1;
    cudaLaunchKernelEx(&cfg, score_kernel, action_logits, target_mean, (float*)out);
}

// round 10
// speedup vs baseline: 1.0078x; 1.0078x over previous
#include <cuda_runtime.h>
#include <math.h>

#define NPROP 1500
#define NACT 64
#define NCLS 81
#define PERSON_IDX 2
#define O_CHUNK 100
#define THREADS 256
#define TILE_F4 ((O_CHUNK * NACT) / 4)   // 1600 float4 per tile

// per-proposal scratch (no cudaMalloc allowed)
__device__ float g_H[NPROP];
__device__ float g_O[NPROP];
__device__ float g_cx[NPROP], g_cy[NPROP];
__device__ float g_iw[NPROP], g_ih[NPROP];
__device__ float g_lw[NPROP], g_lh[NPROP];

// warp-per-row argmax + thread-per-row box stats; 188 blocks -> ~1-2us.
// Triggers the dependent (score) kernel's launch IMMEDIATELY so its fill
// phase executes concurrently with this grid.
__global__ void prep_kernel(const float* __restrict__ scores,
                            const float* __restrict__ bbox) {
    cudaTriggerProgrammaticLaunchCompletion();   // let the score grid start NOW

    const int gtid  = blockIdx.x * blockDim.x + threadIdx.x;
    const int gwarp = gtid >> 5;
    const int lane  = threadIdx.x & 31;

    if (gwarp < NPROP) {
        const float* s = scores + (size_t)gwarp * NCLS;
        float best = s[lane];
        int   bi   = lane;
        float v1 = s[lane + 32];
        if (v1 > best) { best = v1; bi = lane + 32; }
        if (lane + 64 < NCLS) {
            float v2 = s[lane + 64];
            if (v2 > best) { best = v2; bi = lane + 64; }
        }
        #pragma unroll
        for (int sft = 16; sft > 0; sft >>= 1) {
            float ov = __shfl_xor_sync(0xffffffffu, best, sft);
            int   oi = __shfl_xor_sync(0xffffffffu, bi, sft);
            if (ov > best || (ov == best && oi < bi)) { best = ov; bi = oi; }
        }
        if (lane == 0) {
            g_H[gwarp] = (bi == PERSON_IDX) ? best : 0.0f;
            g_O[gwarp] = (bi == PERSON_IDX) ? 0.0f : best;
        }
    }

    if (gtid < NPROP) {
        float x0 = bbox[gtid * 4 + 0], y0 = bbox[gtid * 4 + 1];
        float x1 = bbox[gtid * 4 + 2], y1 = bbox[gtid * 4 + 3];
        float w = x1 - x0, h = y1 - y0;
        g_cx[gtid] = x0 + 0.5f * w;
        g_cy[gtid] = y0 + 0.5f * h;
        g_iw[gtid] = 1.0f / w;
        g_ih[gtid] = 1.0f / h;
        g_lw[gtid] = logf(w);
        g_lh[gtid] = logf(h);
    }
}

// out[h, o, a] = H[h]*O[o]*L[h,a]*exp(-|enc-mu|^2 * k)
//             = O[o] * (H*L*exp(-k*|mu|^2))[a] * exp( dot(enc, 2k*mu[a]) - k*|enc|^2 )
//
// PDL secondary: fill is unconditional (stores start at block start, no input
// dependence, overlapping the prep grid), then cudaGridDependencySynchronize()
// gates the g_H read. Person tiles (~1.2%) overwrite their tile.
__global__ void __launch_bounds__(THREADS, 8)
score_kernel(const float* __restrict__ action_logits,
             const float* __restrict__ target_mean,
             float* __restrict__ out) {
    const int h   = blockIdx.y;
    const int o0  = blockIdx.x * O_CHUNK;
    const int tid = threadIdx.x;

    // 1) unconditional zero-fill: pure STG.128 stream from cycle ~5
    float* blk_out = out + (size_t)h * (NPROP * NACT) + (size_t)o0 * NACT;
    {
        const float4 z = make_float4(0.f, 0.f, 0.f, 0.f);
        float4* p = reinterpret_cast<float4*>(blk_out);
        #pragma unroll 4
        for (int i = tid; i < TILE_F4; i += THREADS)
            p[i] = z;
    }

    // 2) wait for prep grid completion (long done by the time the fill drains)
    cudaGridDependencySynchronize();

    const float H = g_H[h];
    if (H == 0.0f) return;   // 98.8% of blocks retire here

    // ---- rare person path: overwrite the tile ----
    const float K = 5.5555555555555554f;  // 1/(2*0.3^2)

    __shared__ float sM0[NACT], sM1[NACT], sM2[NACT], sM3[NACT], sHQ[NACT];

    if (tid < NACT) {
        const float* mu = target_mean + ((size_t)h * NACT + tid) * 4;
        float m0 = mu[0], m1 = mu[1], m2 = mu[2], m3 = mu[3];
        float msq = m0 * m0 + m1 * m1 + m2 * m2 + m3 * m3;
        float twoK = 2.0f * K;
        sM0[tid] = twoK * m0;
        sM1[tid] = twoK * m1;
        sM2[tid] = twoK * m2;
        sM3[tid] = twoK * m3;
        sHQ[tid] = H * action_logits[(size_t)h * NACT + tid] * __expf(-K * msq);
    }

    const float cxh = g_cx[h], cyh = g_cy[h];
    const float iw = g_iw[h],  ih = g_ih[h];
    const float lw = g_lw[h],  lh = g_lh[h];

    // publishes smem staging AND orders the zero stores before the overwrites
    __syncthreads();

    const int a    = tid & (NACT - 1);
    const int osub = tid >> 6;              // 0..3
    const float M0 = sM0[a], M1 = sM1[a], M2 = sM2[a], M3 = sM3[a];
    const float HQ = sHQ[a];

    for (int j = osub; j < O_CHUNK; j += (THREADS / NACT)) {
        int o = o0 + j;
        float Ov = g_O[o];
        float tx = (g_cx[o] - cxh) * iw;
        float ty = (g_cy[o] - cyh) * ih;
        float tw = g_lw[o] - lw;
        float th = g_lh[o] - lh;
        float e2 = tx * tx + ty * ty + tw * tw + th * th;
        float ex = fmaf(tx, M0, fmaf(ty, M1, fmaf(tw, M2, th * M3))) - K * e2;
        blk_out[(size_t)j * NACT + a] = Ov * HQ * __expf(ex);
    }
}

extern "C" void kernel_launch(void* const* d_in, const int* in_sizes, int n_in,
                              void* d_out, int out_size) {
    const float* action_logits = (const float*)d_in[0];  // [1500,64]
    const float* target_mean   = (const float*)d_in[1];  // [1500,64,4]
    const float* bbox          = (const float*)d_in[2];  // [1500,4]
    const float* scores        = (const float*)d_in[3];  // [1500,81]
    float* out = (float*)d_out;                          // [1500,1500,64]

    // primary: tiny prep (1500 warps, warp-per-row), triggers dependents early
    prep_kernel<<<(NPROP * 32 + THREADS - 1) / THREADS, THREADS>>>(scores, bbox);

    // secondary: PDL — launches as soon as prep triggers; fill overlaps prep
    cudaLaunchConfig_t cfg = {};
    cfg.gridDim  = dim3(NPROP / O_CHUNK, NPROP);  // (15, 1500)
    cfg.blockDim = dim3(THREADS);
    cfg.dynamicSmemBytes = 0;
    cfg.stream = 0;
    cudaLaunchAttribute attr;
    attr.id = cudaLaunchAttributeProgrammaticStreamSerialization;
    attr.val.programmaticStreamSerializationAllowed = 1;
    cfg.attrs = &attr;
    cfg.numAttrs = 1;
    cudaLaunchKernelEx(&cfg, score_kernel, action_logits, target_mean, (float*)out);
}